// round 4
// baseline (speedup 1.0000x reference)
#include <cuda_runtime.h>
#include <cuda_bf16.h>
#include <math_constants.h>

#define Bsz 1024
#define Ssz 128
#define NW (Bsz*Ssz)   // 131072 words

// scratch (static device allocations are allowed)
__device__ float g_xg[2][(size_t)NW*24];  // pre-activations Wih@x + b, per direction
__device__ float g_h[(size_t)NW*12];      // bi-LSTM hidden output [B,S,2H]

__device__ __forceinline__ float tanh_fast(float x){ float y; asm("tanh.approx.f32 %0, %1;" : "=f"(y) : "f"(x)); return y; }

// ---------------- Kernel 1: char-CNN (table-factored) + embeddings + xgate ----------------
// 2 threads per word (one per LSTM direction). 256 threads -> 128 words/block.
// Outputs staged in smem, written back fully coalesced.
__global__ __launch_bounds__(256) void k1_embed(
    const int* __restrict__ word_idx, const int* __restrict__ char_idx,
    const float* __restrict__ word_emb, const float* __restrict__ char_emb,
    const float* __restrict__ Wc, const float* __restrict__ bc,
    const float* __restrict__ Wih_f, const float* __restrict__ b_f,
    const float* __restrict__ Wih_b, const float* __restrict__ b_b)
{
    __shared__ float4 sP[300];       // P[c][k]: 4-filter partial conv dots (bias in k=0)
    __shared__ float4 sW[192];       // [48 gates][4 float4], 14-wide rows padded to 16
    __shared__ float  sB[48];
    __shared__ float  sSt[2][128*25];  // output stage, 25-float padded per word per dir

    int tid = threadIdx.x;
    int wl  = tid >> 1;              // word_local 0..127
    int dir = tid & 1;
    int w   = blockIdx.x*128 + wl;

    // ---- issue per-word global loads FIRST (max MLP, overlap with table build) ----
    int ci[14];
    const int2* cp = (const int2*)(char_idx + (size_t)w*14);
    #pragma unroll
    for (int k=0;k<7;k++){ int2 v = __ldg(cp+k); ci[2*k]=v.x; ci[2*k+1]=v.y; }

    float x[16];
    int widx = __ldg(word_idx + w);
    const float2* wep = (const float2*)(word_emb) + (size_t)widx*5;
    #pragma unroll
    for (int k=0;k<5;k++){ float2 v = __ldg(wep+k); x[2*k]=v.x; x[2*k+1]=v.y; }
    x[14]=0.f; x[15]=0.f;

    // ---- build tables ----
    for (int i = tid; i < 300; i += 256){
        int c = i/3, k = i%3;
        float4 acc;
        if (k==0){ acc.x=__ldg(bc+0); acc.y=__ldg(bc+1); acc.z=__ldg(bc+2); acc.w=__ldg(bc+3); }
        else     { acc.x=0.f; acc.y=0.f; acc.z=0.f; acc.w=0.f; }
        #pragma unroll
        for (int m=0;m<6;m++){
            float e = __ldg(char_emb + c*6 + m);
            acc.x = fmaf(e, __ldg(Wc + 0*18 + k*6 + m), acc.x);
            acc.y = fmaf(e, __ldg(Wc + 1*18 + k*6 + m), acc.y);
            acc.z = fmaf(e, __ldg(Wc + 2*18 + k*6 + m), acc.z);
            acc.w = fmaf(e, __ldg(Wc + 3*18 + k*6 + m), acc.w);
        }
        sP[i] = acc;
    }
    if (tid < 192){
        int g = tid >> 2, q = tid & 3;
        const float* Wih = (g < 24) ? (Wih_f + g*14) : (Wih_b + (g-24)*14);
        int base = q*4;
        float4 wv;
        wv.x = (base+0 < 14) ? __ldg(Wih+base+0) : 0.f;
        wv.y = (base+1 < 14) ? __ldg(Wih+base+1) : 0.f;
        wv.z = (base+2 < 14) ? __ldg(Wih+base+2) : 0.f;
        wv.w = (base+3 < 14) ? __ldg(Wih+base+3) : 0.f;
        sW[tid] = wv;
    }
    if (tid < 48) sB[tid] = (tid < 24) ? __ldg(b_f + tid) : __ldg(b_b + tid - 24);
    __syncthreads();

    // ---- conv + maxpool (lane pairs duplicate: same smem addrs -> broadcast, free) ----
    float4 a = make_float4(-CUDART_INF_F,-CUDART_INF_F,-CUDART_INF_F,-CUDART_INF_F);
    #pragma unroll
    for (int win=0; win<12; win++){
        float4 s0 = sP[ci[win]  *3 + 0];
        float4 s1 = sP[ci[win+1]*3 + 1];
        float4 s2 = sP[ci[win+2]*3 + 2];
        a.x = fmaxf(a.x, s0.x + s1.x + s2.x);
        a.y = fmaxf(a.y, s0.y + s1.y + s2.y);
        a.z = fmaxf(a.z, s0.z + s1.z + s2.z);
        a.w = fmaxf(a.w, s0.w + s1.w + s2.w);
    }
    x[10]=a.x; x[11]=a.y; x[12]=a.z; x[13]=a.w;

    // ---- this thread's direction: 24 gate pre-activations -> staged in smem ----
    int gbase = dir*24;
    float* st = &sSt[dir][wl*25];
    #pragma unroll
    for (int gg=0; gg<24; gg++){
        int g = gbase + gg;
        float acc = sB[g];
        #pragma unroll
        for (int q=0; q<4; q++){
            float4 wv = sW[g*4 + q];
            acc = fmaf(x[4*q+0], wv.x, acc);
            acc = fmaf(x[4*q+1], wv.y, acc);
            acc = fmaf(x[4*q+2], wv.z, acc);
            acc = fmaf(x[4*q+3], wv.w, acc);
        }
        st[gg] = acc;
    }
    __syncthreads();

    // ---- coalesced writeout: 128 words * 24 floats per direction ----
    float* dstf = g_xg[0] + (size_t)blockIdx.x*(128*24);
    float* dstb = g_xg[1] + (size_t)blockIdx.x*(128*24);
    #pragma unroll
    for (int it=0; it<12; it++){
        int lin = it*256 + tid;           // 0..3071
        int adr = lin + lin/24;           // skip padding
        dstf[lin] = sSt[0][adr];
        dstb[lin] = sSt[1][adr];
    }
}

// ---------------- Kernel 2: bidirectional LSTM recurrence ----------------
// one warp per (sentence, direction); lane j<24 owns gate j (torch order i,f,g,o).
// Depth-4 LDG prefetch ring hides xgate read latency; h staged in smem,
// written out coalesced at the end.
__global__ __launch_bounds__(256) void k2_lstm(
    const float* __restrict__ Whh_f, const float* __restrict__ Whh_b)
{
    __shared__ float sH[4*Ssz*12];   // 4 sentences * 128 steps * 12 (both dirs) = 24KB
    const unsigned FULL = 0xffffffffu;
    int tid  = threadIdx.x;
    int warp = tid >> 5;              // 0..7
    int lane = tid & 31;
    int sb   = warp >> 1;             // sentence slot in block 0..3
    int dir  = warp & 1;
    int b    = blockIdx.x*4 + sb;
    int jc   = (lane < 24) ? lane : 0;
    bool is_g = (lane >= 12 && lane < 18);
    float sm = is_g ? 1.f : 0.5f;     // sigmoid(x) = 0.5*tanh(0.5x)+0.5
    float ab = is_g ? 0.f : 0.5f;

    const float* Whh = dir ? Whh_b : Whh_f;
    float w0=__ldg(Whh+jc*6+0), w1=__ldg(Whh+jc*6+1), w2=__ldg(Whh+jc*6+2),
          w3=__ldg(Whh+jc*6+3), w4=__ldg(Whh+jc*6+4), w5=__ldg(Whh+jc*6+5);

    const float* xg = g_xg[dir] + (size_t)b*Ssz*24;
    float* hst = &sH[sb*Ssz*12 + dir*6];

    float h0=0.f,h1=0.f,h2=0.f,h3=0.f,h4=0.f,h5=0.f,c=0.f;
    int s  = dir ? (Ssz-1) : 0;
    int ds = dir ? -1 : 1;

    // prefetch ring (depth 4)
    float pf[4];
    #pragma unroll
    for (int q=0;q<4;q++) pf[q] = __ldg(xg + (s + q*ds)*24 + jc);

    #pragma unroll 4
    for (int t=0; t<Ssz; t++){
        float gcur = pf[t & 3];
        if (t+4 < Ssz) pf[t & 3] = __ldg(xg + (s + 4*ds)*24 + jc);

        float g = fmaf(w0,h0,gcur);
        g = fmaf(w1,h1,g); g = fmaf(w2,h2,g); g = fmaf(w3,h3,g);
        g = fmaf(w4,h4,g); g = fmaf(w5,h5,g);
        float act = fmaf(sm, tanh_fast(g*sm), ab);   // tanh for g-gate, sigmoid otherwise

        // lanes 0-5: act is their own i-gate; gather f,g,o
        float af = __shfl_sync(FULL, act, lane+6);
        float ag = __shfl_sync(FULL, act, lane+12);
        float ao = __shfl_sync(FULL, act, lane+18);
        c = fmaf(af, c, act*ag);
        float hj = ao * tanh_fast(c);

        h0=__shfl_sync(FULL,hj,0); h1=__shfl_sync(FULL,hj,1); h2=__shfl_sync(FULL,hj,2);
        h3=__shfl_sync(FULL,hj,3); h4=__shfl_sync(FULL,hj,4); h5=__shfl_sync(FULL,hj,5);

        if (lane < 6) hst[s*12 + lane] = hj;
        s += ds;
    }
    __syncthreads();

    // coalesced writeout of 4 sentences (6144 floats) as float4
    float4* dst = (float4*)(g_h + (size_t)blockIdx.x*(4*Ssz*12));
    const float4* src = (const float4*)sH;
    #pragma unroll
    for (int it=0; it<6; it++)
        dst[it*256 + tid] = src[it*256 + tid];
}

// ---------------- Kernel 3: tag linear + log_softmax (weights in registers) --------
// warp per 16 (b,s) pairs; each thread owns 5 tag columns kept in registers.
__global__ __launch_bounds__(256) void k3_tag(
    const float* __restrict__ Wt, const float* __restrict__ bt, float* __restrict__ out)
{
    int tid = threadIdx.x, lane = tid & 31, warp = tid >> 5;

    float w[5][12], bs[5];
    #pragma unroll
    for (int t5=0; t5<5; t5++){
        int j = lane + 32*t5;
        bool valid = (j < 135);
        bs[t5] = valid ? __ldg(bt + j) : -1e30f;   // exp(-1e30)=0, drops out of sum
        #pragma unroll
        for (int k=0;k<12;k++) w[t5][k] = valid ? __ldg(Wt + j*12 + k) : 0.f;
    }

    int base = (blockIdx.x*8 + warp)*16;
    for (int it=0; it<16; it++){
        int p = base + it;
        const float4* hp = (const float4*)(g_h + (size_t)p*12);  // 48B stride, 16B aligned
        float4 h0 = __ldg(hp+0), h1 = __ldg(hp+1), h2 = __ldg(hp+2);
        float h[12] = {h0.x,h0.y,h0.z,h0.w, h1.x,h1.y,h1.z,h1.w, h2.x,h2.y,h2.z,h2.w};

        // |v| is bounded (|h|<1, small weights): safe to skip the max-shift
        float tg[5]; float zs = 0.f;
        #pragma unroll
        for (int t5=0; t5<5; t5++){
            float v = bs[t5];
            #pragma unroll
            for (int k=0;k<12;k++) v = fmaf(h[k], w[t5][k], v);
            tg[t5] = v;
            zs += __expf(v);
        }
        #pragma unroll
        for (int o=16;o>0;o>>=1) zs += __shfl_xor_sync(0xffffffffu, zs, o);
        float lse = __logf(zs);

        float* op = out + (size_t)p*135;
        #pragma unroll
        for (int t5=0; t5<5; t5++){
            int j = lane + 32*t5;
            if (j < 135) op[j] = tg[t5] - lse;
        }
    }
}

// ---------------- Launch ----------------
extern "C" void kernel_launch(void* const* d_in, const int* in_sizes, int n_in,
                              void* d_out, int out_size)
{
    const int *word_idx=nullptr,*char_idx=nullptr;
    const float *word_emb=nullptr,*char_emb=nullptr,*Wc=nullptr,*bc=nullptr,
        *Wih_f=nullptr,*Whh_f=nullptr,*b_f=nullptr,
        *Wih_b=nullptr,*Whh_b=nullptr,*b_b=nullptr,*Wt=nullptr,*bt=nullptr;
    for (int i=0;i<n_in;i++){
        int sz = in_sizes[i]; const void* p = d_in[i];
        switch (sz){
            case 131072:  word_idx=(const int*)p; break;          // [B,S]
            case 1835008: char_idx=(const int*)p; break;          // [B,S,LP]
            case 500000:  word_emb=(const float*)p; break;        // [V,WE]
            case 600:     char_emb=(const float*)p; break;        // [A,CE]
            case 72:      Wc=(const float*)p; break;              // [Lf,K*CE]
            case 4:       bc=(const float*)p; break;              // [Lf]
            case 336:     if(!Wih_f) Wih_f=(const float*)p; else Wih_b=(const float*)p; break;
            case 144:     if(!Whh_f) Whh_f=(const float*)p; else Whh_b=(const float*)p; break;
            case 24:      if(!b_f)   b_f  =(const float*)p; else b_b  =(const float*)p; break;
            case 1620:    Wt=(const float*)p; break;              // [T,2H]
            case 135:     bt=(const float*)p; break;              // [T]
        }
    }

    k1_embed<<<NW/128, 256>>>(word_idx, char_idx, word_emb, char_emb,
                              Wc, bc, Wih_f, b_f, Wih_b, b_b);
    k2_lstm<<<(2*Bsz*32)/256, 256>>>(Whh_f, Whh_b);   // 2048 warps, 8/block
    k3_tag<<<NW/128, 256>>>(Wt, bt, (float*)d_out);
    (void)out_size; (void)n_in;
}

// round 5
// speedup vs baseline: 1.1251x; 1.1251x over previous
#include <cuda_runtime.h>
#include <cuda_bf16.h>
#include <math_constants.h>

#define Bsz 1024
#define Ssz 128
#define NW (Bsz*Ssz)   // 131072 words

__device__ __forceinline__ float tanh_fast(float x){ float y; asm("tanh.approx.f32 %0, %1;" : "=f"(y) : "f"(x)); return y; }

// ============ fully fused: one block per sentence, 256 threads ============
// Phase A: char-CNN + embeddings + xgate pre-activations -> smem
// Phase B: warps 0/1 run fwd/bwd LSTM from smem -> smem h
// Phase C: tag linear + log_softmax from smem h -> out
__global__ __launch_bounds__(256) void fused_tagger(
    const int* __restrict__ word_idx, const int* __restrict__ char_idx,
    const float* __restrict__ word_emb, const float* __restrict__ char_emb,
    const float* __restrict__ Wc, const float* __restrict__ bc,
    const float* __restrict__ Wih_f, const float* __restrict__ b_f,
    const float* __restrict__ Wih_b, const float* __restrict__ b_b,
    const float* __restrict__ Whh_f, const float* __restrict__ Whh_b,
    const float* __restrict__ Wt, const float* __restrict__ bt,
    float* __restrict__ out)
{
    __shared__ float4 sP[300];     // conv partial-dot table, bias folded into k=0
    __shared__ float4 sW[192];     // [48 gates][4 float4], 14-wide rows padded to 16
    __shared__ float  sB[48];
    __shared__ float  sXG[6416];   // [2][128 words x 25 pad] (+8 pad between dirs)
    __shared__ float  sH[Ssz*12];  // hidden states, both dirs

    const unsigned FULL = 0xffffffffu;
    int tid  = threadIdx.x;
    int lane = tid & 31;
    int warp = tid >> 5;
    int blk  = blockIdx.x;         // sentence

    // ---- per-word global loads first (max MLP; overlap with table build) ----
    int wl  = tid >> 1;            // word in sentence 0..127
    int dir = tid & 1;
    size_t w = (size_t)blk*Ssz + wl;

    int ci[14];
    const int2* cp = (const int2*)(char_idx + w*14);
    #pragma unroll
    for (int k=0;k<7;k++){ int2 v = __ldg(cp+k); ci[2*k]=v.x; ci[2*k+1]=v.y; }

    float x[16];
    int widx = __ldg(word_idx + w);
    const float2* wep = (const float2*)(word_emb) + (size_t)widx*5;
    #pragma unroll
    for (int k=0;k<5;k++){ float2 v = __ldg(wep+k); x[2*k]=v.x; x[2*k+1]=v.y; }
    x[14]=0.f; x[15]=0.f;

    // ---- build tables ----
    for (int i = tid; i < 300; i += 256){
        int c = i/3, k = i%3;
        float4 acc;
        if (k==0){ acc.x=__ldg(bc+0); acc.y=__ldg(bc+1); acc.z=__ldg(bc+2); acc.w=__ldg(bc+3); }
        else     { acc.x=0.f; acc.y=0.f; acc.z=0.f; acc.w=0.f; }
        #pragma unroll
        for (int m=0;m<6;m++){
            float e = __ldg(char_emb + c*6 + m);
            acc.x = fmaf(e, __ldg(Wc + 0*18 + k*6 + m), acc.x);
            acc.y = fmaf(e, __ldg(Wc + 1*18 + k*6 + m), acc.y);
            acc.z = fmaf(e, __ldg(Wc + 2*18 + k*6 + m), acc.z);
            acc.w = fmaf(e, __ldg(Wc + 3*18 + k*6 + m), acc.w);
        }
        sP[i] = acc;
    }
    if (tid < 192){
        int g = tid >> 2, q = tid & 3;
        const float* Wih = (g < 24) ? (Wih_f + g*14) : (Wih_b + (g-24)*14);
        int base = q*4;
        float4 wv;
        wv.x = (base+0 < 14) ? __ldg(Wih+base+0) : 0.f;
        wv.y = (base+1 < 14) ? __ldg(Wih+base+1) : 0.f;
        wv.z = (base+2 < 14) ? __ldg(Wih+base+2) : 0.f;
        wv.w = (base+3 < 14) ? __ldg(Wih+base+3) : 0.f;
        sW[tid] = wv;
    }
    if (tid < 48) sB[tid] = (tid < 24) ? __ldg(b_f + tid) : __ldg(b_b + tid - 24);
    __syncthreads();

    // ---- Phase A: conv + maxpool (pair threads duplicate; same smem addr = broadcast) ----
    float4 a = make_float4(-CUDART_INF_F,-CUDART_INF_F,-CUDART_INF_F,-CUDART_INF_F);
    #pragma unroll
    for (int win=0; win<12; win++){
        float4 s0 = sP[ci[win]  *3 + 0];
        float4 s1 = sP[ci[win+1]*3 + 1];
        float4 s2 = sP[ci[win+2]*3 + 2];
        a.x = fmaxf(a.x, s0.x + s1.x + s2.x);
        a.y = fmaxf(a.y, s0.y + s1.y + s2.y);
        a.z = fmaxf(a.z, s0.z + s1.z + s2.z);
        a.w = fmaxf(a.w, s0.w + s1.w + s2.w);
    }
    x[10]=a.x; x[11]=a.y; x[12]=a.z; x[13]=a.w;

    // xgates for this thread's direction -> smem
    {
        int gbase = dir*24;
        float* st = &sXG[dir*3208 + wl*25];
        #pragma unroll
        for (int gg=0; gg<24; gg++){
            int g = gbase + gg;
            float acc = sB[g];
            #pragma unroll
            for (int q=0; q<4; q++){
                float4 wv = sW[g*4 + q];
                acc = fmaf(x[4*q+0], wv.x, acc);
                acc = fmaf(x[4*q+1], wv.y, acc);
                acc = fmaf(x[4*q+2], wv.z, acc);
                acc = fmaf(x[4*q+3], wv.w, acc);
            }
            st[gg] = acc;
        }
    }
    __syncthreads();

    // ---- Phase B: LSTM recurrence, warp 0 = forward, warp 1 = backward ----
    if (warp < 2){
        int d   = warp;
        int jc  = (lane < 24) ? lane : 0;
        bool is_g = (lane >= 12 && lane < 18);
        float sm = is_g ? 1.f : 0.5f;     // sigmoid(x) = 0.5*tanh(0.5x)+0.5
        float ab = is_g ? 0.f : 0.5f;

        const float* Whh = d ? Whh_b : Whh_f;
        float w0=__ldg(Whh+jc*6+0), w1=__ldg(Whh+jc*6+1), w2=__ldg(Whh+jc*6+2),
              w3=__ldg(Whh+jc*6+3), w4=__ldg(Whh+jc*6+4), w5=__ldg(Whh+jc*6+5);

        const float* xgp = &sXG[d*3208];
        float h0=0.f,h1=0.f,h2=0.f,h3=0.f,h4=0.f,h5=0.f,c=0.f;
        int s  = d ? (Ssz-1) : 0;
        int ds = d ? -1 : 1;

        #pragma unroll 4
        for (int t=0; t<Ssz; t++){
            float gcur = xgp[s*25 + jc];     // conflict-free LDS, lat ~29

            float g = fmaf(w0,h0,gcur);
            g = fmaf(w1,h1,g); g = fmaf(w2,h2,g); g = fmaf(w3,h3,g);
            g = fmaf(w4,h4,g); g = fmaf(w5,h5,g);
            float act = fmaf(sm, tanh_fast(g*sm), ab);

            float af = __shfl_sync(FULL, act, lane+6);
            float ag = __shfl_sync(FULL, act, lane+12);
            float ao = __shfl_sync(FULL, act, lane+18);
            c = fmaf(af, c, act*ag);
            float hj = ao * tanh_fast(c);

            h0=__shfl_sync(FULL,hj,0); h1=__shfl_sync(FULL,hj,1); h2=__shfl_sync(FULL,hj,2);
            h3=__shfl_sync(FULL,hj,3); h4=__shfl_sync(FULL,hj,4); h5=__shfl_sync(FULL,hj,5);

            if (lane < 6) sH[s*12 + d*6 + lane] = hj;
            s += ds;
        }
    }
    __syncthreads();

    // ---- Phase C: tag linear + log_softmax, weights in registers ----
    float wt[5][12], bs[5];
    #pragma unroll
    for (int t5=0; t5<5; t5++){
        int j = lane + 32*t5;
        bool valid = (j < 135);
        bs[t5] = valid ? __ldg(bt + j) : -1e30f;   // exp(-1e30)=0, drops out of sum
        #pragma unroll
        for (int k=0;k<12;k++) wt[t5][k] = valid ? __ldg(Wt + j*12 + k) : 0.f;
    }

    int base = warp*16;
    for (int it=0; it<16; it++){
        int p = base + it;
        const float4* hp = (const float4*)(sH + p*12);   // 48B stride, 16B aligned, broadcast
        float4 h0v = hp[0], h1v = hp[1], h2v = hp[2];
        float h[12] = {h0v.x,h0v.y,h0v.z,h0v.w, h1v.x,h1v.y,h1v.z,h1v.w, h2v.x,h2v.y,h2v.z,h2v.w};

        // |v| bounded (|h|<1, small weights): safe to skip max-shift
        float tg[5]; float zs = 0.f;
        #pragma unroll
        for (int t5=0; t5<5; t5++){
            float v = bs[t5];
            #pragma unroll
            for (int k=0;k<12;k++) v = fmaf(h[k], wt[t5][k], v);
            tg[t5] = v;
            zs += __expf(v);
        }
        #pragma unroll
        for (int o=16;o>0;o>>=1) zs += __shfl_xor_sync(FULL, zs, o);
        float lse = __logf(zs);

        float* op = out + ((size_t)blk*Ssz + p)*135;
        #pragma unroll
        for (int t5=0; t5<5; t5++){
            int j = lane + 32*t5;
            if (j < 135) op[j] = tg[t5] - lse;
        }
    }
}

// ---------------- Launch ----------------
extern "C" void kernel_launch(void* const* d_in, const int* in_sizes, int n_in,
                              void* d_out, int out_size)
{
    const int *word_idx=nullptr,*char_idx=nullptr;
    const float *word_emb=nullptr,*char_emb=nullptr,*Wc=nullptr,*bc=nullptr,
        *Wih_f=nullptr,*Whh_f=nullptr,*b_f=nullptr,
        *Wih_b=nullptr,*Whh_b=nullptr,*b_b=nullptr,*Wt=nullptr,*bt=nullptr;
    for (int i=0;i<n_in;i++){
        int sz = in_sizes[i]; const void* p = d_in[i];
        switch (sz){
            case 131072:  word_idx=(const int*)p; break;          // [B,S]
            case 1835008: char_idx=(const int*)p; break;          // [B,S,LP]
            case 500000:  word_emb=(const float*)p; break;        // [V,WE]
            case 600:     char_emb=(const float*)p; break;        // [A,CE]
            case 72:      Wc=(const float*)p; break;              // [Lf,K*CE]
            case 4:       bc=(const float*)p; break;              // [Lf]
            case 336:     if(!Wih_f) Wih_f=(const float*)p; else Wih_b=(const float*)p; break;
            case 144:     if(!Whh_f) Whh_f=(const float*)p; else Whh_b=(const float*)p; break;
            case 24:      if(!b_f)   b_f  =(const float*)p; else b_b  =(const float*)p; break;
            case 1620:    Wt=(const float*)p; break;              // [T,2H]
            case 135:     bt=(const float*)p; break;              // [T]
        }
    }

    fused_tagger<<<Bsz, 256>>>(word_idx, char_idx, word_emb, char_emb,
                               Wc, bc, Wih_f, b_f, Wih_b, b_b,
                               Whh_f, Whh_b, Wt, bt, (float*)d_out);
    (void)out_size; (void)n_in;
}